// round 2
// baseline (speedup 1.0000x reference)
#include <cuda_runtime.h>
#include <math.h>

#define BATCH 128
#define SEQ   80
#define EMB_D 100
#define UNITS 1024
#define G4    4096   // 4*UNITS

// ---------------- scratch (device globals; no allocations) ----------------
__device__ float g_XW1[(size_t)SEQ * BATCH * G4];   // precomputed x@W1+b1, [T][B][4096]
__device__ float g_h1A[BATCH * UNITS];
__device__ float g_h1B[BATCH * UNITS];
__device__ float g_c1 [BATCH * UNITS];
__device__ float g_h2A[BATCH * UNITS];
__device__ float g_h2B[BATCH * UNITS];
__device__ float g_c2 [BATCH * UNITS];

__device__ __forceinline__ float sigf(float x) { return 1.0f / (1.0f + expf(-x)); }

// ---------------- zero the recurrent state (every graph replay) ----------------
__global__ void zero_state_kernel(float* a, float* b, float* c, float* d, int n) {
    int i = blockIdx.x * blockDim.x + threadIdx.x;
    if (i < n) { a[i] = 0.f; b[i] = 0.f; c[i] = 0.f; d[i] = 0.f; }
}

// ---------------- XW1 = emb[x] @ W1 + b1 for all (t,b) ----------------
// M = T*B = 10240 rows (m = t*128 + b), K = 100, N = 4096.
// Tiles: 64x64, BK=20 (100 = 5*20), 256 threads, 4x4 per thread.
__global__ void xw1_kernel(const int* __restrict__ x, const float* __restrict__ emb,
                           const float* __restrict__ W1, const float* __restrict__ b1,
                           float* __restrict__ XW1) {
    __shared__ float a_s[20][64];   // [k][m]
    __shared__ float b_s[20][64];   // [k][n]
    const int n0 = blockIdx.x * 64;
    const int m0 = blockIdx.y * 64;
    const int tid = threadIdx.x;
    const int ty = tid >> 4, tx = tid & 15;

    float acc[4][4];
#pragma unroll
    for (int i = 0; i < 4; ++i)
#pragma unroll
        for (int j = 0; j < 4; ++j) acc[i][j] = 0.f;

    for (int k0 = 0; k0 < EMB_D; k0 += 20) {
#pragma unroll
        for (int i = 0; i < 5; ++i) {
            int e = tid + i * 256;          // 0..1279 covers 20x64
            int k = e >> 6, r = e & 63;
            int m = m0 + r;
            int bb = m & 127, t = m >> 7;
            int tok = x[bb * SEQ + t];
            a_s[k][r] = emb[tok * EMB_D + k0 + k];
            b_s[k][r] = W1[(k0 + k) * G4 + n0 + r];
        }
        __syncthreads();
#pragma unroll
        for (int k = 0; k < 20; ++k) {
            float aR[4], bR[4];
#pragma unroll
            for (int i = 0; i < 4; ++i) aR[i] = a_s[k][ty * 4 + i];
#pragma unroll
            for (int j = 0; j < 4; ++j) bR[j] = b_s[k][tx * 4 + j];
#pragma unroll
            for (int i = 0; i < 4; ++i)
#pragma unroll
                for (int j = 0; j < 4; ++j) acc[i][j] += aR[i] * bR[j];
        }
        __syncthreads();
    }
#pragma unroll
    for (int i = 0; i < 4; ++i)
#pragma unroll
        for (int j = 0; j < 4; ++j) {
            int m = m0 + ty * 4 + i;
            int n = n0 + tx * 4 + j;
            XW1[(size_t)m * G4 + n] = acc[i][j] + b1[n];
        }
}

// ---------------- one LSTM step, fused GEMM + gates ----------------
// z[b, g*1024+u] = (optional zbase) + (optional xin@Wx, K=1024) + hprev@Umat (K=1024) + (optional bias)
// Block: 32 batch rows x 32 units x all 4 gates (128 z-cols). Grid (32, 4) = 128 blocks.
// 256 threads: ty = tid/32 (warp id, 4 rows each), tx = tid%32 (one unit, all 4 gates).
__global__ void lstm_step_kernel(const float* __restrict__ zbase,  // [B, 4096] slice or null
                                 const float* __restrict__ bias,   // [4096] or null
                                 const float* __restrict__ xin,    // [B, 1024] or null
                                 const float* __restrict__ Wx,     // [1024, 4096]
                                 const float* __restrict__ hprev,  // [B, 1024]
                                 const float* __restrict__ Umat,   // [1024, 4096]
                                 float* __restrict__ c_state,      // [B, 1024]
                                 float* __restrict__ h_out) {      // [B, 1024]
    __shared__ float a_s[32][16];    // [row][k]
    __shared__ float b_s[16][128];   // [k][gate*32+u]
    const int u0 = blockIdx.x * 32;
    const int m0 = blockIdx.y * 32;
    const int tid = threadIdx.x;
    const int ty = tid >> 5;         // 0..7
    const int tx = tid & 31;         // 0..31

    float acc[4][4];
#pragma unroll
    for (int i = 0; i < 4; ++i)
#pragma unroll
        for (int g = 0; g < 4; ++g) acc[i][g] = 0.f;

    for (int p = 0; p < 2; ++p) {
        const float* A  = (p == 0) ? xin : hprev;
        const float* Bm = (p == 0) ? Wx  : Umat;
        if (A == nullptr) continue;
        for (int k0 = 0; k0 < UNITS; k0 += 16) {
            {   // load A tile: 32x16 = 512 elems, 2 per thread
                int e = tid;
                int r = e >> 4, k = e & 15;
                a_s[r][k] = A[(m0 + r) * UNITS + k0 + k];
                e = tid + 256;
                r = e >> 4; k = e & 15;
                a_s[r][k] = A[(m0 + r) * UNITS + k0 + k];
            }
#pragma unroll
            for (int i = 0; i < 8; ++i) {  // load B tile: 16x128 = 2048 elems
                int e = tid + i * 256;
                int k = e >> 7, c = e & 127;
                int col = (c >> 5) * UNITS + u0 + (c & 31);
                b_s[k][c] = Bm[(k0 + k) * G4 + col];
            }
            __syncthreads();
#pragma unroll
            for (int k = 0; k < 16; ++k) {
                float aR[4], bR[4];
#pragma unroll
                for (int i = 0; i < 4; ++i) aR[i] = a_s[ty * 4 + i][k];  // broadcast in warp
#pragma unroll
                for (int g = 0; g < 4; ++g) bR[g] = b_s[k][g * 32 + tx]; // conflict-free
#pragma unroll
                for (int i = 0; i < 4; ++i)
#pragma unroll
                    for (int g = 0; g < 4; ++g) acc[i][g] += aR[i] * bR[g];
            }
            __syncthreads();
        }
    }

    const int u = u0 + tx;
#pragma unroll
    for (int i = 0; i < 4; ++i) {
        int br = m0 + ty * 4 + i;
        float zi = acc[i][0], zf = acc[i][1], zg = acc[i][2], zo = acc[i][3];
        if (zbase != nullptr) {
            const float* zb = zbase + (size_t)br * G4;
            zi += zb[u]; zf += zb[UNITS + u]; zg += zb[2 * UNITS + u]; zo += zb[3 * UNITS + u];
        }
        if (bias != nullptr) {
            zi += bias[u]; zf += bias[UNITS + u]; zg += bias[2 * UNITS + u]; zo += bias[3 * UNITS + u];
        }
        float ig = sigf(zi);
        float fg = sigf(zf);
        float gg = tanhf(zg);
        float og = sigf(zo);
        int idx = br * UNITS + u;
        float c = fg * c_state[idx] + ig * gg;
        c_state[idx] = c;
        h_out[idx] = og * tanhf(c);
    }
}

// ---------------- final: sigmoid(h2_last @ Wfc + bfc) ----------------
__global__ void final_kernel(const float* __restrict__ h2, const float* __restrict__ Wfc,
                             const float* __restrict__ bfc, float* __restrict__ out) {
    const int b = blockIdx.x;
    const int tid = threadIdx.x;   // 128 threads
    float s = 0.f;
#pragma unroll
    for (int k = 0; k < 8; ++k) {
        int u = tid + k * 128;
        s += h2[b * UNITS + u] * Wfc[u];
    }
#pragma unroll
    for (int o = 16; o > 0; o >>= 1) s += __shfl_down_sync(0xffffffffu, s, o);
    __shared__ float ws[4];
    if ((tid & 31) == 0) ws[tid >> 5] = s;
    __syncthreads();
    if (tid == 0) {
        float tot = ws[0] + ws[1] + ws[2] + ws[3] + bfc[0];
        out[b] = 1.0f / (1.0f + expf(-tot));
    }
}

// ---------------- launcher ----------------
extern "C" void kernel_launch(void* const* d_in, const int* in_sizes, int n_in,
                              void* d_out, int out_size) {
    const int*   x   = (const int*)d_in[0];
    const float* emb = (const float*)d_in[1];
    const float* W1  = (const float*)d_in[2];
    const float* U1  = (const float*)d_in[3];
    const float* b1  = (const float*)d_in[4];
    const float* W2  = (const float*)d_in[5];
    const float* U2  = (const float*)d_in[6];
    const float* b2  = (const float*)d_in[7];
    const float* Wfc = (const float*)d_in[8];
    const float* bfc = (const float*)d_in[9];
    float* out = (float*)d_out;

    float *XW1p, *h1A, *h1B, *c1, *h2A, *h2B, *c2;
    cudaGetSymbolAddress((void**)&XW1p, g_XW1);
    cudaGetSymbolAddress((void**)&h1A, g_h1A);
    cudaGetSymbolAddress((void**)&h1B, g_h1B);
    cudaGetSymbolAddress((void**)&c1,  g_c1);
    cudaGetSymbolAddress((void**)&h2A, g_h2A);
    cudaGetSymbolAddress((void**)&h2B, g_h2B);
    cudaGetSymbolAddress((void**)&c2,  g_c2);

    // reset recurrent state (graph is replayed; must be deterministic)
    zero_state_kernel<<<(BATCH * UNITS + 255) / 256, 256>>>(h1A, c1, h2A, c2, BATCH * UNITS);

    // precompute layer-1 input projection for all timesteps
    xw1_kernel<<<dim3(G4 / 64, (SEQ * BATCH) / 64), 256>>>(x, emb, W1, b1, XW1p);

    for (int t = 0; t < SEQ; ++t) {
        float* h1r = (t & 1) ? h1B : h1A;
        float* h1w = (t & 1) ? h1A : h1B;
        float* h2r = (t & 1) ? h2B : h2A;
        float* h2w = (t & 1) ? h2A : h2B;
        // layer 1: z = XW1[t] + h1 @ U1   (bias already folded into XW1)
        lstm_step_kernel<<<dim3(32, 4), 256>>>(XW1p + (size_t)t * BATCH * G4,
                                               nullptr, nullptr, nullptr,
                                               h1r, U1, c1, h1w);
        // layer 2: z = h1_t @ W2 + h2 @ U2 + b2
        lstm_step_kernel<<<dim3(32, 4), 256>>>(nullptr, b2,
                                               h1w, W2,
                                               h2r, U2, c2, h2w);
    }

    // SEQ even -> last write landed in the 'A' buffers
    final_kernel<<<BATCH, 128>>>(h2A, Wfc, bfc, out);
}

// round 3
// speedup vs baseline: 3.0862x; 3.0862x over previous
#include <cuda_runtime.h>
#include <cuda_fp16.h>
#include <math.h>

#define BATCH 128
#define SEQ   80
#define EMB_D 100
#define UNITS 1024
#define G4    4096
#define NBLK  128      // persistent blocks, 8 units each

// ---------------- device scratch ----------------
__device__ float  g_XW1[(size_t)SEQ * BATCH * G4];      // x@W1+b1 for all t (fp32)
__device__ __half g_U1h[(size_t)UNITS * G4];            // packed per-block [bx][k][32]
__device__ __half g_W2h[(size_t)UNITS * G4];
__device__ __half g_U2h[(size_t)UNITS * G4];
__device__ __half g_h1[2][BATCH * UNITS];
__device__ __half g_h2[2][BATCH * UNITS];
__device__ float  g_c1[BATCH * UNITS];
__device__ float  g_c2[BATCH * UNITS];
__device__ unsigned g_cnt;
__device__ unsigned g_gen;

__device__ __forceinline__ float sigf(float x) { return 1.0f / (1.0f + expf(-x)); }

// ---------------- PTX helpers ----------------
__device__ __forceinline__ unsigned smem_u32(const void* p) {
    return (unsigned)__cvta_generic_to_shared(p);
}
__device__ __forceinline__ void ldsm_x4(unsigned& r0, unsigned& r1, unsigned& r2, unsigned& r3,
                                        unsigned addr) {
    asm volatile("ldmatrix.sync.aligned.m8n8.x4.shared.b16 {%0,%1,%2,%3}, [%4];\n"
                 : "=r"(r0), "=r"(r1), "=r"(r2), "=r"(r3) : "r"(addr));
}
__device__ __forceinline__ void ldsm_x4t(unsigned& r0, unsigned& r1, unsigned& r2, unsigned& r3,
                                         unsigned addr) {
    asm volatile("ldmatrix.sync.aligned.m8n8.x4.trans.shared.b16 {%0,%1,%2,%3}, [%4];\n"
                 : "=r"(r0), "=r"(r1), "=r"(r2), "=r"(r3) : "r"(addr));
}
__device__ __forceinline__ void mma16816(float* d, const unsigned* a, unsigned b0, unsigned b1) {
    asm volatile(
        "mma.sync.aligned.m16n8k16.row.col.f32.f16.f16.f32 "
        "{%0,%1,%2,%3},{%4,%5,%6,%7},{%8,%9},{%0,%1,%2,%3};\n"
        : "+f"(d[0]), "+f"(d[1]), "+f"(d[2]), "+f"(d[3])
        : "r"(a[0]), "r"(a[1]), "r"(a[2]), "r"(a[3]), "r"(b0), "r"(b1));
}

// ---------------- init (every replay: deterministic state) ----------------
__global__ void init_kernel() {
    int i = blockIdx.x * blockDim.x + threadIdx.x;
    if (i == 0) { g_cnt = 0; g_gen = 0; }
    if (i < BATCH * UNITS) {
        g_h1[0][i] = __float2half(0.f); g_h1[1][i] = __float2half(0.f);
        g_h2[0][i] = __float2half(0.f); g_h2[1][i] = __float2half(0.f);
        g_c1[i] = 0.f; g_c2[i] = 0.f;
    }
}

// ---------------- pack W -> fp16 per-block slices: dst[bx][k][g*8+ui] ----------------
__global__ void pack_kernel(const float* __restrict__ U1, const float* __restrict__ W2,
                            const float* __restrict__ U2) {
    const size_t total = (size_t)UNITS * G4;
    for (size_t i = blockIdx.x * blockDim.x + threadIdx.x; i < total;
         i += (size_t)gridDim.x * blockDim.x) {
        int c  = (int)(i & 31);
        int k  = (int)((i >> 5) & 1023);
        int bx = (int)(i >> 15);
        size_t src = (size_t)k * G4 + (c >> 3) * UNITS + bx * 8 + (c & 7);
        g_U1h[i] = __float2half(U1[src]);
        g_W2h[i] = __float2half(W2[src]);
        g_U2h[i] = __float2half(U2[src]);
    }
}

// ---------------- XW1 = emb[x] @ W1 + b1 (verified in R1) ----------------
__global__ void xw1_kernel(const int* __restrict__ x, const float* __restrict__ emb,
                           const float* __restrict__ W1, const float* __restrict__ b1,
                           float* __restrict__ XW1) {
    __shared__ float a_s[20][64];
    __shared__ float b_s[20][64];
    const int n0 = blockIdx.x * 64;
    const int m0 = blockIdx.y * 64;
    const int tid = threadIdx.x;
    const int ty = tid >> 4, tx = tid & 15;
    float acc[4][4];
#pragma unroll
    for (int i = 0; i < 4; ++i)
#pragma unroll
        for (int j = 0; j < 4; ++j) acc[i][j] = 0.f;
    for (int k0 = 0; k0 < EMB_D; k0 += 20) {
#pragma unroll
        for (int i = 0; i < 5; ++i) {
            int e = tid + i * 256;
            int k = e >> 6, r = e & 63;
            int m = m0 + r;
            int bb = m & 127, t = m >> 7;
            int tok = x[bb * SEQ + t];
            a_s[k][r] = emb[tok * EMB_D + k0 + k];
            b_s[k][r] = W1[(k0 + k) * G4 + n0 + r];
        }
        __syncthreads();
#pragma unroll
        for (int k = 0; k < 20; ++k) {
            float aR[4], bR[4];
#pragma unroll
            for (int i = 0; i < 4; ++i) aR[i] = a_s[k][ty * 4 + i];
#pragma unroll
            for (int j = 0; j < 4; ++j) bR[j] = b_s[k][tx * 4 + j];
#pragma unroll
            for (int i = 0; i < 4; ++i)
#pragma unroll
                for (int j = 0; j < 4; ++j) acc[i][j] += aR[i] * bR[j];
        }
        __syncthreads();
    }
#pragma unroll
    for (int i = 0; i < 4; ++i)
#pragma unroll
        for (int j = 0; j < 4; ++j) {
            int m = m0 + ty * 4 + i;
            int n = n0 + tx * 4 + j;
            XW1[(size_t)m * G4 + n] = acc[i][j] + b1[n];
        }
}

// ---------------- grid barrier (sense-counting, 128 resident blocks) ----------------
__device__ __forceinline__ void grid_barrier(unsigned phase) {
    __threadfence();
    __syncthreads();
    if (threadIdx.x == 0) {
        unsigned old = atomicAdd(&g_cnt, 1u);
        if (old == NBLK - 1) {
            g_cnt = 0;
            __threadfence();
            atomicExch(&g_gen, phase);
        } else {
            while (atomicAdd(&g_gen, 0u) < phase) __nanosleep(64);
        }
    }
    __syncthreads();
    __threadfence();
}

// SMEM geometry: A tile 128x64 halves @ stride 72, B tile 64x32 halves @ stride 40,
// z tile 128x32 floats @ stride 33 (aliases A region).
#define SA_STRIDE 72
#define SB_STRIDE 40
#define SA_BYTES  (128 * SA_STRIDE * 2)   // 18432
#define SB_BYTES  (64 * SB_STRIDE * 2)    // 5120

// K=1024 segment: acc += A[128x1024] @ B[1024x32]
__device__ __forceinline__ void mma_segment(const __half* __restrict__ A,
                                            const __half* __restrict__ Bp,
                                            float acc[2][2][4],
                                            __half* sA, __half* sB,
                                            int wm, int wn, int lane) {
    const int tid = threadIdx.x;
    const int ar = tid >> 1, asel = tid & 1;        // A loader: half-row each
    const int bkr = tid >> 2, bco = (tid & 3) * 8;  // B loader: 16B each
    for (int kc = 0; kc < UNITS; kc += 64) {
        const uint4* ga = (const uint4*)(A + ar * UNITS + kc + asel * 32);
        uint4* da = (uint4*)(sA + ar * SA_STRIDE + asel * 32);
        da[0] = ga[0]; da[1] = ga[1]; da[2] = ga[2]; da[3] = ga[3];
        *(uint4*)(sB + bkr * SB_STRIDE + bco) = *(const uint4*)(Bp + (size_t)(kc + bkr) * 32 + bco);
        __syncthreads();
#pragma unroll
        for (int ks = 0; ks < 4; ++ks) {
            unsigned a0[4], a1[4], b[4];
            unsigned aa0 = smem_u32(sA + (wm * 32 + (lane & 15)) * SA_STRIDE + ks * 16 + (lane >> 4) * 8);
            ldsm_x4(a0[0], a0[1], a0[2], a0[3], aa0);
            ldsm_x4(a1[0], a1[1], a1[2], a1[3], aa0 + 16 * SA_STRIDE * 2);
            unsigned ba = smem_u32(sB + (ks * 16 + (lane & 15)) * SB_STRIDE + wn * 16 + (lane >> 4) * 8);
            ldsm_x4t(b[0], b[1], b[2], b[3], ba);
            mma16816(acc[0][0], a0, b[0], b[1]);
            mma16816(acc[0][1], a0, b[2], b[3]);
            mma16816(acc[1][0], a1, b[0], b[1]);
            mma16816(acc[1][1], a1, b[2], b[3]);
        }
        __syncthreads();
    }
}

// one fused block-step: z = A0@B0 (+A1@B1) (+zbase)(+bias); gates; c,h update
__device__ __forceinline__ void block_step(const __half* A0, const __half* B0,
                                           const __half* A1, const __half* B1,
                                           const float* zbase, const float* bias,
                                           float* cst, __half* hout, int u0,
                                           __half* sA, __half* sB, float* zs) {
    const int lane = threadIdx.x & 31;
    const int w = threadIdx.x >> 5;
    const int wm = w >> 1, wn = w & 1;
    float acc[2][2][4];
#pragma unroll
    for (int a = 0; a < 2; ++a)
#pragma unroll
        for (int b = 0; b < 2; ++b)
#pragma unroll
            for (int i = 0; i < 4; ++i) acc[a][b][i] = 0.f;

    mma_segment(A0, B0, acc, sA, sB, wm, wn, lane);
    if (A1) mma_segment(A1, B1, acc, sA, sB, wm, wn, lane);

    // spill z tiles to smem (zs aliases sA; safe: mainloop ended with __syncthreads)
#pragma unroll
    for (int mt = 0; mt < 2; ++mt)
#pragma unroll
        for (int nt = 0; nt < 2; ++nt)
#pragma unroll
            for (int i = 0; i < 4; ++i) {
                int rr = wm * 32 + mt * 16 + (lane >> 2) + (i >> 1) * 8;
                int cc = wn * 16 + nt * 8 + (lane & 3) * 2 + (i & 1);
                zs[rr * 33 + cc] = acc[mt][nt][i];
            }
    __syncthreads();

    // gate fusion: 256 threads -> 128 rows x 8 units
    const int r = threadIdx.x >> 1;
    const int ub = (threadIdx.x & 1) * 4;
#pragma unroll
    for (int j = 0; j < 4; ++j) {
        int ui = ub + j;
        int u = u0 + ui;
        float zi = zs[r * 33 + ui];
        float zf = zs[r * 33 + 8 + ui];
        float zg = zs[r * 33 + 16 + ui];
        float zo = zs[r * 33 + 24 + ui];
        if (zbase) {
            const float* zb = zbase + (size_t)r * G4;
            zi += zb[u]; zf += zb[UNITS + u]; zg += zb[2 * UNITS + u]; zo += zb[3 * UNITS + u];
        }
        if (bias) {
            zi += bias[u]; zf += bias[UNITS + u]; zg += bias[2 * UNITS + u]; zo += bias[3 * UNITS + u];
        }
        float ig = sigf(zi), fg = sigf(zf), gg = tanhf(zg), og = sigf(zo);
        int idx = r * UNITS + u;
        float c = fg * cst[idx] + ig * gg;
        cst[idx] = c;
        hout[idx] = __float2half(og * tanhf(c));
    }
}

// ---------------- persistent recurrence: one launch, 160 grid barriers ----------------
__global__ void __launch_bounds__(256, 1) lstm_persist(const float* __restrict__ b2) {
    __shared__ __align__(16) char smraw[SA_BYTES + SB_BYTES];
    __half* sA = (__half*)smraw;
    __half* sB = (__half*)(smraw + SA_BYTES);
    float* zs = (float*)smraw;          // aliases sA

    const int bx = blockIdx.x;
    const int u0 = bx * 8;
    const __half* U1p = g_U1h + (size_t)bx * UNITS * 32;
    const __half* W2p = g_W2h + (size_t)bx * UNITS * 32;
    const __half* U2p = g_U2h + (size_t)bx * UNITS * 32;

    unsigned phase = 0;
    for (int t = 0; t < SEQ; ++t) {
        const __half* h1r = g_h1[t & 1];
        __half*       h1w = g_h1[(t & 1) ^ 1];
        const __half* h2r = g_h2[t & 1];
        __half*       h2w = g_h2[(t & 1) ^ 1];

        // layer 1: z = XW1[t] + h1 @ U1
        block_step(h1r, U1p, nullptr, nullptr,
                   g_XW1 + (size_t)t * BATCH * G4, nullptr,
                   g_c1, h1w, u0, sA, sB, zs);
        grid_barrier(++phase);

        // layer 2: z = h1_t @ W2 + h2 @ U2 + b2
        block_step(h1w, W2p, h2r, U2p,
                   nullptr, b2,
                   g_c2, h2w, u0, sA, sB, zs);
        grid_barrier(++phase);
    }
}

// ---------------- final dense + sigmoid ----------------
__global__ void final_kernel(const float* __restrict__ Wfc, const float* __restrict__ bfc,
                             float* __restrict__ out) {
    const int b = blockIdx.x;
    const int tid = threadIdx.x;  // 128
    const __half* h2 = g_h2[0];   // SEQ=80 even -> last write in buf 0
    float s = 0.f;
#pragma unroll
    for (int k = 0; k < 8; ++k) {
        int u = tid + k * 128;
        s += __half2float(h2[b * UNITS + u]) * Wfc[u];
    }
#pragma unroll
    for (int o = 16; o > 0; o >>= 1) s += __shfl_down_sync(0xffffffffu, s, o);
    __shared__ float ws[4];
    if ((tid & 31) == 0) ws[tid >> 5] = s;
    __syncthreads();
    if (tid == 0) {
        float tot = ws[0] + ws[1] + ws[2] + ws[3] + bfc[0];
        out[b] = 1.0f / (1.0f + expf(-tot));
    }
}

// ---------------- launcher ----------------
extern "C" void kernel_launch(void* const* d_in, const int* in_sizes, int n_in,
                              void* d_out, int out_size) {
    const int*   x   = (const int*)d_in[0];
    const float* emb = (const float*)d_in[1];
    const float* W1  = (const float*)d_in[2];
    const float* U1  = (const float*)d_in[3];
    const float* b1  = (const float*)d_in[4];
    const float* W2  = (const float*)d_in[5];
    const float* U2  = (const float*)d_in[6];
    const float* b2  = (const float*)d_in[7];
    const float* Wfc = (const float*)d_in[8];
    const float* bfc = (const float*)d_in[9];
    float* out = (float*)d_out;

    float* XW1p;
    cudaGetSymbolAddress((void**)&XW1p, g_XW1);

    init_kernel<<<(BATCH * UNITS + 255) / 256, 256>>>();
    xw1_kernel<<<dim3(G4 / 64, (SEQ * BATCH) / 64), 256>>>(x, emb, W1, b1, XW1p);
    pack_kernel<<<4096, 256>>>(U1, W2, U2);
    lstm_persist<<<NBLK, 256>>>(b2);
    final_kernel<<<BATCH, 128>>>(Wfc, bfc, out);
}

// round 5
// speedup vs baseline: 6.8409x; 2.2166x over previous
#include <cuda_runtime.h>
#include <cuda_fp16.h>
#include <math.h>

#define BATCH 128
#define SEQ   80
#define EMB_D 100
#define UNITS 1024
#define G4    4096
#define NBLK  128
#define KPAD  112

// ---------------- device scratch ----------------
__device__ __align__(16) float  g_XW1[(size_t)SEQ * BATCH * G4];
__device__ __align__(16) __half g_Eh[(size_t)SEQ * BATCH * KPAD];   // gathered emb, K padded
__device__ __align__(16) __half g_W1h[(size_t)KPAD * G4];
__device__ __align__(16) __half g_B1h[(size_t)NBLK * UNITS * 64];   // [bx][k][ U1(32) | W2(32) ]
__device__ __align__(16) __half g_B2h[(size_t)NBLK * UNITS * 32];   // [bx][k][ U2(32) ]
__device__ __align__(16) __half g_h1[2][BATCH * UNITS];
__device__ __align__(16) __half g_h2[2][BATCH * UNITS];
__device__ float g_c1[BATCH * UNITS];
__device__ float g_c2[BATCH * UNITS];
__device__ unsigned g_cnt;
__device__ unsigned g_gen;

__device__ __forceinline__ float sigf(float x) { return 1.0f / (1.0f + expf(-x)); }

// ---------------- PTX helpers ----------------
__device__ __forceinline__ unsigned smem_u32(const void* p) {
    return (unsigned)__cvta_generic_to_shared(p);
}
__device__ __forceinline__ void ldsm_x4(unsigned& r0, unsigned& r1, unsigned& r2, unsigned& r3,
                                        unsigned addr) {
    asm volatile("ldmatrix.sync.aligned.m8n8.x4.shared.b16 {%0,%1,%2,%3}, [%4];\n"
                 : "=r"(r0), "=r"(r1), "=r"(r2), "=r"(r3) : "r"(addr));
}
__device__ __forceinline__ void ldsm_x4t(unsigned& r0, unsigned& r1, unsigned& r2, unsigned& r3,
                                         unsigned addr) {
    asm volatile("ldmatrix.sync.aligned.m8n8.x4.trans.shared.b16 {%0,%1,%2,%3}, [%4];\n"
                 : "=r"(r0), "=r"(r1), "=r"(r2), "=r"(r3) : "r"(addr));
}
__device__ __forceinline__ void mma16816(float* d, const unsigned* a, unsigned b0, unsigned b1) {
    asm volatile(
        "mma.sync.aligned.m16n8k16.row.col.f32.f16.f16.f32 "
        "{%0,%1,%2,%3},{%4,%5,%6,%7},{%8,%9},{%0,%1,%2,%3};\n"
        : "+f"(d[0]), "+f"(d[1]), "+f"(d[2]), "+f"(d[3])
        : "r"(a[0]), "r"(a[1]), "r"(a[2]), "r"(a[3]), "r"(b0), "r"(b1));
}
__device__ __forceinline__ void cpa16(unsigned dst, const void* src) {
    asm volatile("cp.async.cg.shared.global [%0], [%1], 16;\n" :: "r"(dst), "l"(src));
}
__device__ __forceinline__ void cp_commit() { asm volatile("cp.async.commit_group;\n"); }
__device__ __forceinline__ void cp_wait1() { asm volatile("cp.async.wait_group 1;\n"); }
__device__ __forceinline__ void cp_wait0() { asm volatile("cp.async.wait_group 0;\n"); }

// ---------------- init (deterministic per replay) ----------------
__global__ void init_kernel() {
    int i = blockIdx.x * blockDim.x + threadIdx.x;
    if (i == 0) { g_cnt = 0; g_gen = 0; }
    if (i < BATCH * UNITS) {
        g_h1[0][i] = __float2half(0.f); g_h1[1][i] = __float2half(0.f);
        g_h2[0][i] = __float2half(0.f); g_h2[1][i] = __float2half(0.f);
        g_c1[i] = 0.f; g_c2[i] = 0.f;
    }
}

// ---------------- gather embedding rows -> fp16 [m][112] ----------------
__global__ void gather_emb(const int* __restrict__ x, const float* __restrict__ emb) {
    int m = blockIdx.x;                 // m = t*128 + b
    int tid = threadIdx.x;              // 128
    int b = m & 127, t = m >> 7;
    int tok = x[b * SEQ + t];
    if (tid < KPAD)
        g_Eh[(size_t)m * KPAD + tid] =
            __float2half(tid < EMB_D ? emb[(size_t)tok * EMB_D + tid] : 0.f);
}

__global__ void pack_w1(const float* __restrict__ W1) {
    int k = blockIdx.x;                 // 0..111
    for (int n = threadIdx.x; n < G4; n += blockDim.x)
        g_W1h[(size_t)k * G4 + n] = __float2half(k < EMB_D ? W1[(size_t)k * G4 + n] : 0.f);
}

// ---------------- pack recurrent weights into per-block fp16 slices ----------------
__global__ void pack_b(const float* __restrict__ U1, const float* __restrict__ W2,
                       const float* __restrict__ U2) {
    const size_t tot1 = (size_t)NBLK * UNITS * 64;
    for (size_t i = blockIdx.x * (size_t)blockDim.x + threadIdx.x; i < tot1;
         i += (size_t)gridDim.x * blockDim.x) {
        int c  = (int)(i & 63);
        int k  = (int)((i >> 6) & 1023);
        int bx = (int)(i >> 16);
        int cc = c & 31;
        size_t src = (size_t)k * G4 + (cc >> 3) * UNITS + bx * 8 + (cc & 7);
        g_B1h[i] = __float2half(c < 32 ? U1[src] : W2[src]);
    }
    const size_t tot2 = (size_t)NBLK * UNITS * 32;
    for (size_t i = blockIdx.x * (size_t)blockDim.x + threadIdx.x; i < tot2;
         i += (size_t)gridDim.x * blockDim.x) {
        int c  = (int)(i & 31);
        int k  = (int)((i >> 5) & 1023);
        int bx = (int)(i >> 15);
        size_t src = (size_t)k * G4 + (c >> 3) * UNITS + bx * 8 + (c & 7);
        g_B2h[i] = __float2half(U2[src]);
    }
}

// ---------------- XW1 = Eh @ W1h + b1 (tensor cores, K=112) ----------------
__global__ void __launch_bounds__(256) xw1_mma(const float* __restrict__ b1,
                                               float* __restrict__ XW1) {
    __shared__ __align__(16) __half sA[128 * 120];   // stride 120 halves
    __shared__ __align__(16) __half sB[112 * 72];    // stride 72 halves
    const int n0 = blockIdx.x * 64, m0 = blockIdx.y * 128;
    const int tid = threadIdx.x, lane = tid & 31, w = tid >> 5;
    const int wm = w >> 1, wn = w & 1;

    {   // A: 2 threads per row, 7 x 16B each
        int r = tid >> 1, part = tid & 1;
        const uint4* src = (const uint4*)(g_Eh + (size_t)(m0 + r) * KPAD + part * 56);
        uint4* dst = (uint4*)(sA + r * 120 + part * 56);
#pragma unroll
        for (int j = 0; j < 7; ++j) dst[j] = src[j];
    }
#pragma unroll
    for (int j = 0; j < 4; ++j) {       // B: 112x64 halves = 896 x 16B
        int idx = tid + j * 256;
        if (idx < 896) {
            int k = idx >> 3, c = idx & 7;
            *(uint4*)(sB + k * 72 + c * 8) = *(const uint4*)(g_W1h + (size_t)k * G4 + n0 + c * 8);
        }
    }
    __syncthreads();

    float acc[2][4][4];
#pragma unroll
    for (int a = 0; a < 2; ++a)
#pragma unroll
        for (int b = 0; b < 4; ++b)
#pragma unroll
            for (int i = 0; i < 4; ++i) acc[a][b][i] = 0.f;

#pragma unroll
    for (int ks = 0; ks < 7; ++ks) {
        unsigned a0[4], a1r[4], bA[4], bB[4];
        unsigned ar = smem_u32(sA) + (wm * 32 + (lane & 15)) * 240 + ks * 32 + (lane >> 4) * 16;
        ldsm_x4(a0[0], a0[1], a0[2], a0[3], ar);
        ldsm_x4(a1r[0], a1r[1], a1r[2], a1r[3], ar + 16 * 240);
        unsigned br = smem_u32(sB) + (ks * 16 + (lane & 15)) * 144 + wn * 64 + (lane >> 4) * 16;
        ldsm_x4t(bA[0], bA[1], bA[2], bA[3], br);
        ldsm_x4t(bB[0], bB[1], bB[2], bB[3], br + 32);
        mma16816(acc[0][0], a0, bA[0], bA[1]);
        mma16816(acc[0][1], a0, bA[2], bA[3]);
        mma16816(acc[0][2], a0, bB[0], bB[1]);
        mma16816(acc[0][3], a0, bB[2], bB[3]);
        mma16816(acc[1][0], a1r, bA[0], bA[1]);
        mma16816(acc[1][1], a1r, bA[2], bA[3]);
        mma16816(acc[1][2], a1r, bB[0], bB[1]);
        mma16816(acc[1][3], a1r, bB[2], bB[3]);
    }
#pragma unroll
    for (int mt = 0; mt < 2; ++mt)
#pragma unroll
        for (int nt = 0; nt < 4; ++nt)
#pragma unroll
            for (int i = 0; i < 4; ++i) {
                int rr = m0 + wm * 32 + mt * 16 + (lane >> 2) + (i >> 1) * 8;
                int cc = n0 + wn * 32 + nt * 8 + (lane & 3) * 2 + (i & 1);
                XW1[(size_t)rr * G4 + cc] = acc[mt][nt][i] + b1[cc];
            }
}

// ---------------- grid barrier (sense via monotonically increasing phase) ----------------
__device__ __forceinline__ void grid_barrier(unsigned phase) {
    __threadfence();
    __syncthreads();
    if (threadIdx.x == 0) {
        unsigned old = atomicAdd(&g_cnt, 1u);
        if (old == NBLK - 1) {
            g_cnt = 0;
            __threadfence();
            atomicExch(&g_gen, phase);
        } else {
            while (atomicAdd(&g_gen, 0u) < phase) __nanosleep(32);
        }
    }
    __syncthreads();
    __threadfence();
}

// stage layout (bytes): A1[128x72h]=18432 | A2=18432 | B1[64x72h]=9216 | B2[64x40h]=5120
#define O_A2 18432
#define O_B1 36864
#define O_B2 46080
#define STAGE 51200

// z spill scratch (aliases stage memory; only live between trailing __syncthreads
// of the mainloop and the grid barrier): zs1 is 128 rows x 64 cols, stride 68.
#define ZS1_STRIDE 68
#define ZS2_STRIDE 36

__device__ __forceinline__ void issue_chunk(const __half* A1, const __half* A2,
                                            const __half* B1p, const __half* B2p,
                                            int kc, char* st, int tid) {
    unsigned b = smem_u32(st);
#pragma unroll
    for (int j = 0; j < 4; ++j) {           // A1: 128x64 halves
        int idx = tid + j * 256; int r = idx >> 3, c = idx & 7;
        cpa16(b + r * 144 + c * 16, A1 + r * UNITS + kc + c * 8);
    }
#pragma unroll
    for (int j = 0; j < 4; ++j) {           // A2
        int idx = tid + j * 256; int r = idx >> 3, c = idx & 7;
        cpa16(b + O_A2 + r * 144 + c * 16, A2 + r * UNITS + kc + c * 8);
    }
#pragma unroll
    for (int j = 0; j < 2; ++j) {           // B1: 64x64 halves
        int idx = tid + j * 256; int k = idx >> 3, c = idx & 7;
        cpa16(b + O_B1 + k * 144 + c * 16, B1p + (size_t)(kc + k) * 64 + c * 8);
    }
    {                                        // B2: 64x32 halves
        int k = tid >> 2, c = tid & 3;
        cpa16(b + O_B2 + k * 80 + c * 16, B2p + (size_t)(kc + k) * 32 + c * 8);
    }
}

__device__ __forceinline__ void compute_chunk(char* st, float acc1[2][4][4], float acc2[4][4],
                                              int wm, int wn, int w, int lane) {
    unsigned ab = smem_u32(st);
#pragma unroll
    for (int ks = 0; ks < 4; ++ks) {
        unsigned a0[4], a1r[4], a2r[4], bA[4], bB[4], b2a[4], b2b[4];
        unsigned arow = ab + (wm * 32 + (lane & 15)) * 144 + ks * 32 + (lane >> 4) * 16;
        ldsm_x4(a0[0], a0[1], a0[2], a0[3], arow);
        ldsm_x4(a1r[0], a1r[1], a1r[2], a1r[3], arow + 16 * 144);
        unsigned a2row = ab + O_A2 + (w * 16 + (lane & 15)) * 144 + ks * 32 + (lane >> 4) * 16;
        ldsm_x4(a2r[0], a2r[1], a2r[2], a2r[3], a2row);
        unsigned brow = ab + O_B1 + (ks * 16 + (lane & 15)) * 144 + wn * 64 + (lane >> 4) * 16;
        ldsm_x4t(bA[0], bA[1], bA[2], bA[3], brow);
        ldsm_x4t(bB[0], bB[1], bB[2], bB[3], brow + 32);
        unsigned b2row = ab + O_B2 + (ks * 16 + (lane & 15)) * 80 + (lane >> 4) * 16;
        ldsm_x4t(b2a[0], b2a[1], b2a[2], b2a[3], b2row);
        ldsm_x4t(b2b[0], b2b[1], b2b[2], b2b[3], b2row + 32);

        mma16816(acc1[0][0], a0, bA[0], bA[1]);
        mma16816(acc1[0][1], a0, bA[2], bA[3]);
        mma16816(acc1[0][2], a0, bB[0], bB[1]);
        mma16816(acc1[0][3], a0, bB[2], bB[3]);
        mma16816(acc1[1][0], a1r, bA[0], bA[1]);
        mma16816(acc1[1][1], a1r, bA[2], bA[3]);
        mma16816(acc1[1][2], a1r, bB[0], bB[1]);
        mma16816(acc1[1][3], a1r, bB[2], bB[3]);
        mma16816(acc2[0], a2r, b2a[0], b2a[1]);
        mma16816(acc2[1], a2r, b2a[2], b2a[3]);
        mma16816(acc2[2], a2r, b2b[0], b2b[1]);
        mma16816(acc2[3], a2r, b2b[2], b2b[3]);
    }
}

// ---------------- persistent fused 2-layer recurrence, 81 ticks ----------------
extern __shared__ __align__(16) char dynsm[];
__global__ void __launch_bounds__(256, 1) lstm_persist(const float* __restrict__ b2) {
    char* smem = dynsm;
    const int tid = threadIdx.x, lane = tid & 31, w = tid >> 5;
    const int wm = w >> 1, wn = w & 1;
    const int bx = blockIdx.x, u0 = bx * 8;
    const __half* B1p = g_B1h + (size_t)bx * UNITS * 64;
    const __half* B2p = g_B2h + (size_t)bx * UNITS * 32;
    float* zs1 = (float*)smem;                        // 128 x 64, stride 68
    float* zs2 = zs1 + 128 * ZS1_STRIDE;              // 128 x 32, stride 36

    for (int s = 0; s <= SEQ; ++s) {
        // tick s: layer1 computes h1[s] from h1[s-1]; layer2 computes h2[s-1]
        // from h1[s-1] (same A tile) and h2[s-2].
        const __half* A1 = g_h1[(s & 1) ^ 1];
        const __half* A2 = g_h2[s & 1];
        __half* h1w = g_h1[s & 1];
        __half* h2w = g_h2[(s & 1) ^ 1];

        float acc1[2][4][4]; float acc2[4][4];
#pragma unroll
        for (int a = 0; a < 2; ++a)
#pragma unroll
            for (int b = 0; b < 4; ++b)
#pragma unroll
                for (int i = 0; i < 4; ++i) acc1[a][b][i] = 0.f;
#pragma unroll
        for (int b = 0; b < 4; ++b)
#pragma unroll
            for (int i = 0; i < 4; ++i) acc2[b][i] = 0.f;

        issue_chunk(A1, A2, B1p, B2p, 0, smem, tid);
        cp_commit();
        for (int kc = 0; kc < 16; ++kc) {
            if (kc < 15) {
                issue_chunk(A1, A2, B1p, B2p, (kc + 1) * 64, smem + ((kc + 1) & 1) * STAGE, tid);
                cp_commit();
                cp_wait1();
            } else {
                cp_wait0();
            }
            __syncthreads();
            compute_chunk(smem + (kc & 1) * STAGE, acc1, acc2, wm, wn, w, lane);
            __syncthreads();
        }

        // spill z tiles (aliases stages; dead until next tick's issue_chunk,
        // which happens only after the grid barrier below)
#pragma unroll
        for (int mt = 0; mt < 2; ++mt)
#pragma unroll
            for (int nt = 0; nt < 4; ++nt)
#pragma unroll
                for (int i = 0; i < 4; ++i) {
                    int rr = wm * 32 + mt * 16 + (lane >> 2) + (i >> 1) * 8;
                    int cc = wn * 32 + nt * 8 + (lane & 3) * 2 + (i & 1);
                    zs1[rr * ZS1_STRIDE + cc] = acc1[mt][nt][i];
                }
#pragma unroll
        for (int nt = 0; nt < 4; ++nt)
#pragma unroll
            for (int i = 0; i < 4; ++i) {
                int rr = w * 16 + (lane >> 2) + (i >> 1) * 8;
                int cc = nt * 8 + (lane & 3) * 2 + (i & 1);
                zs2[rr * ZS2_STRIDE + cc] = acc2[nt][i];
            }
        __syncthreads();

        // gates: 2 threads per batch row; zs1 cols 0..31 = h1@U1 (this block's
        // 8 units x 4 gates), cols 32..63 = h1@W2; zs2 = h2@U2.
        const int r = tid >> 1;
        const int hp = (tid & 1) * 4;
        if (s < SEQ) {
            const float* zb = g_XW1 + (size_t)s * BATCH * G4 + (size_t)r * G4;
#pragma unroll
            for (int j = 0; j < 4; ++j) {
                int ui = hp + j;
                int u = u0 + ui;
                float zi = zs1[r * ZS1_STRIDE + ui]      + zb[u];
                float zf = zs1[r * ZS1_STRIDE + 8 + ui]  + zb[UNITS + u];
                float zg = zs1[r * ZS1_STRIDE + 16 + ui] + zb[2 * UNITS + u];
                float zo = zs1[r * ZS1_STRIDE + 24 + ui] + zb[3 * UNITS + u];
                int idx = r * UNITS + u;
                float c = sigf(zf) * g_c1[idx] + sigf(zi) * tanhf(zg);
                g_c1[idx] = c;
                h1w[idx] = __float2half(sigf(zo) * tanhf(c));
            }
        }
        if (s > 0) {
#pragma unroll
            for (int j = 0; j < 4; ++j) {
                int ui = hp + j;
                int u = u0 + ui;
                float zi = zs1[r * ZS1_STRIDE + 32 + ui] + zs2[r * ZS2_STRIDE + ui]      + b2[u];
                float zf = zs1[r * ZS1_STRIDE + 40 + ui] + zs2[r * ZS2_STRIDE + 8 + ui]  + b2[UNITS + u];
                float zg = zs1[r * ZS1_STRIDE + 48 + ui] + zs2[r * ZS2_STRIDE + 16 + ui] + b2[2 * UNITS + u];
                float zo = zs1[r * ZS1_STRIDE + 56 + ui] + zs2[r * ZS2_STRIDE + 24 + ui] + b2[3 * UNITS + u];
                int idx = r * UNITS + u;
                float c = sigf(zf) * g_c2[idx] + sigf(zi) * tanhf(zg);
                g_c2[idx] = c;
                h2w[idx] = __float2half(sigf(zo) * tanhf(c));
            }
        }
        grid_barrier((unsigned)(s + 1));
    }
}

// ---------------- final dense + sigmoid ----------------
__global__ void final_kernel(const float* __restrict__ Wfc, const float* __restrict__ bfc,
                             float* __restrict__ out) {
    const int b = blockIdx.x;
    const int tid = threadIdx.x;   // 128
    const __half* h2 = g_h2[1];    // h2[79] lives in buffer (80&1)^1 = 1
    float s = 0.f;
#pragma unroll
    for (int k = 0; k < 8; ++k) {
        int u = tid + k * 128;
        s += __half2float(h2[b * UNITS + u]) * Wfc[u];
    }
#pragma unroll
    for (int o = 16; o > 0; o >>= 1) s += __shfl_down_sync(0xffffffffu, s, o);
    __shared__ float ws[4];
    if ((tid & 31) == 0) ws[tid >> 5] = s;
    __syncthreads();
    if (tid == 0) {
        float tot = ws[0] + ws[1] + ws[2] + ws[3] + bfc[0];
        out[b] = 1.0f / (1.0f + expf(-tot));
    }
}

// ---------------- launcher ----------------
extern "C" void kernel_launch(void* const* d_in, const int* in_sizes, int n_in,
                              void* d_out, int out_size) {
    const int*   x   = (const int*)d_in[0];
    const float* emb = (const float*)d_in[1];
    const float* W1  = (const float*)d_in[2];
    const float* U1  = (const float*)d_in[3];
    const float* b1  = (const float*)d_in[4];
    const float* W2  = (const float*)d_in[5];
    const float* U2  = (const float*)d_in[6];
    const float* b2  = (const float*)d_in[7];
    const float* Wfc = (const float*)d_in[8];
    const float* bfc = (const float*)d_in[9];
    float* out = (float*)d_out;

    float* XW1p;
    cudaGetSymbolAddress((void**)&XW1p, g_XW1);

    cudaFuncSetAttribute((const void*)lstm_persist,
                         cudaFuncAttributeMaxDynamicSharedMemorySize, 2 * STAGE);

    init_kernel<<<512, 256>>>();
    gather_emb<<<SEQ * BATCH, 128>>>(x, emb);
    pack_w1<<<KPAD, 256>>>(W1);
    pack_b<<<2048, 256>>>(U1, W2, U2);
    xw1_mma<<<dim3(G4 / 64, SEQ * BATCH / 128), 256>>>(b1, XW1p);
    lstm_persist<<<NBLK, 256, 2 * STAGE>>>(b2);
    final_kernel<<<BATCH, 128>>>(Wfc, bfc, out);
}